// round 6
// baseline (speedup 1.0000x reference)
#include <cuda_runtime.h>
#include <cstdint>

// TranVectorQuantizer: latent [16384,8,32] f32, codebook [128,32] f32.
// Outputs concatenated in d_out (all f32):
//   [0,        4194304)  policy_vq_latent = latent + (quantized - latent)
//   [4194304,  8388608)  quantized_latent = codebook[argmin_j dist(x, c_j)]
//   [8388608, 75497472)  codebook_set = codebook tiled 16384x
//
// Distance reproduces the reference arithmetic EXACTLY (rel_err 0.0 verified):
//   d_j = fmaf(-2, M_j, fl(A + B_j)), fixed f32x2 FMA chain order for M_j.
// DO NOT change the FMA chain order or the snapping add: tie-breaking on the
// ~ulp(32) distance grid depends on it.
//
// R5 structure: 2 rows per thread so each codebook LDS (the dominant L1TEX
// consumer at 89% in R4) feeds two dot chains; codebook_set broadcast stores
// stay interleaved with the argmin loop (2 per code) to overlap DRAM drain.

#define DDIM 32
#define KCODES 128

static __device__ __forceinline__ unsigned long long pk2(float a, float b) {
    unsigned long long r;
    asm("mov.b64 %0, {%1, %2};" : "=l"(r) : "f"(a), "f"(b));
    return r;
}
static __device__ __forceinline__ void upk2(unsigned long long p, float& a, float& b) {
    asm("mov.b64 {%0, %1}, %2;" : "=f"(a), "=f"(b) : "l"(p));
}
static __device__ __forceinline__ void fma2(unsigned long long& acc,
                                            unsigned long long x,
                                            unsigned long long c) {
    asm("fma.rn.f32x2 %0, %1, %2, %0;" : "+l"(acc) : "l"(x), "l"(c));
}

// ---------------- exact kernel: n_rows % 128 == 0, 2 rows/thread ------------
__global__ void __launch_bounds__(64, 8) vq_fused2_kernel(
    const float* __restrict__ latent,
    const float* __restrict__ cb,
    float* __restrict__ out,
    int n_rows)
{
    __shared__ float s_cb[KCODES * DDIM];   // 16 KB
    __shared__ float s_nrm[KCODES];

    const int tid  = threadIdx.x;
    const int gt   = blockIdx.x * 64 + tid;          // global thread id
    const int rowA = blockIdx.x * 128 + tid;
    const int rowB = rowA + 64;

    // ---- issue both latent rows early (overlaps codebook staging) ----
    const float4* la = reinterpret_cast<const float4*>(latent) + (size_t)rowA * 8;
    const float4* lb = reinterpret_cast<const float4*>(latent) + (size_t)rowB * 8;
    float4 xa[8], xb[8];
    #pragma unroll
    for (int k = 0; k < 8; k++) { xa[k] = la[k]; xb[k] = lb[k]; }

    // ---- stage codebook ----
    float4* s_cb4 = reinterpret_cast<float4*>(s_cb);
    const float4* cb4 = reinterpret_cast<const float4*>(cb);
    #pragma unroll
    for (int i = 0; i < 16; i++) s_cb4[tid + i * 64] = cb4[tid + i * 64];
    __syncthreads();

    #pragma unroll
    for (int h = 0; h < 2; h++) {        // same per-code accumulation order as R4
        int c = tid + h * 64;
        float s = 0.f;
        #pragma unroll
        for (int d = 0; d < DDIM; d++) { float v = s_cb[c * DDIM + d]; s += v * v; }
        s_nrm[c] = s;
    }
    __syncthreads();

    // ---- pack rows + A (identical numerics per row to R4) ----
    unsigned long long xA0[8], xA1[8], xB0[8], xB1[8];
    float AA, AB;
    {
        float a0 = 0.f, a1 = 0.f, a2 = 0.f, a3 = 0.f;
        #pragma unroll
        for (int k = 0; k < 8; k++) {
            a0 = fmaf(xa[k].x, xa[k].x, a0);
            a1 = fmaf(xa[k].y, xa[k].y, a1);
            a2 = fmaf(xa[k].z, xa[k].z, a2);
            a3 = fmaf(xa[k].w, xa[k].w, a3);
            xA0[k] = pk2(xa[k].x, xa[k].y);
            xA1[k] = pk2(xa[k].z, xa[k].w);
        }
        AA = (a0 + a1) + (a2 + a3);
    }
    {
        float a0 = 0.f, a1 = 0.f, a2 = 0.f, a3 = 0.f;
        #pragma unroll
        for (int k = 0; k < 8; k++) {
            a0 = fmaf(xb[k].x, xb[k].x, a0);
            a1 = fmaf(xb[k].y, xb[k].y, a1);
            a2 = fmaf(xb[k].z, xb[k].z, a2);
            a3 = fmaf(xb[k].w, xb[k].w, a3);
            xB0[k] = pk2(xb[k].x, xb[k].y);
            xB1[k] = pk2(xb[k].z, xb[k].w);
        }
        AB = (a0 + a1) + (a2 + a3);
    }

    const size_t n_lat = (size_t)n_rows * DDIM;
    float* out_quant = out + n_lat;
    float4* out_cs4  = reinterpret_cast<float4*>(out + 2 * n_lat);
    const size_t nth = (size_t)gridDim.x * 64;       // == n_rows/2, multiple of 1024

    float bestA = 3.0e38f, bestB = 3.0e38f;
    int   biA = 0, biB = 0;
    const ulonglong2* scb2 = reinterpret_cast<const ulonglong2*>(s_cb);

    // stride preserves (index & 1023): one register-held broadcast value
    float4 vbc = s_cb4[gt & 1023];
    float4* csp = out_cs4 + gt;

    for (int j = 0; j < KCODES; j++) {
        __stcs(csp, vbc);                 // 2 interleaved codebook_set stores
        __stcs(csp + nth, vbc);
        csp += 2 * nth;

        unsigned long long aA0 = 0ull, aA1 = 0ull, aB0 = 0ull, aB1 = 0ull;
        const ulonglong2* cj = scb2 + j * 8;          // broadcast LDS, shared by both rows
        #pragma unroll
        for (int k = 0; k < 8; k++) {
            ulonglong2 c = cj[k];
            fma2(aA0, xA0[k], c.x);
            fma2(aA1, xA1[k], c.y);
            fma2(aB0, xB0[k], c.x);
            fma2(aB1, xB1[k], c.y);
        }
        float nrm = s_nrm[j];
        unsigned long long sA, sB;
        asm("add.rn.f32x2 %0, %1, %2;" : "=l"(sA) : "l"(aA0), "l"(aA1));
        asm("add.rn.f32x2 %0, %1, %2;" : "=l"(sB) : "l"(aB0), "l"(aB1));
        float lo, hi;
        upk2(sA, lo, hi);
        float dA = fmaf(-2.0f, lo + hi, AA + nrm);    // fl(S - 2M), single rounding
        upk2(sB, lo, hi);
        float dB = fmaf(-2.0f, lo + hi, AB + nrm);
        if (dA < bestA) { bestA = dA; biA = j; }      // strict <: first index on ties
        if (dB < bestB) { bestB = dB; biB = j; }
    }

    // ---- write quantized + policy for both rows (x from packs: bit-identical) ----
    {
        const float4* qa = reinterpret_cast<const float4*>(s_cb + biA * DDIM);
        const float4* qb = reinterpret_cast<const float4*>(s_cb + biB * DDIM);
        float4* oqA = reinterpret_cast<float4*>(out_quant) + (size_t)rowA * 8;
        float4* opA = reinterpret_cast<float4*>(out)       + (size_t)rowA * 8;
        float4* oqB = reinterpret_cast<float4*>(out_quant) + (size_t)rowB * 8;
        float4* opB = reinterpret_cast<float4*>(out)       + (size_t)rowB * 8;
        #pragma unroll
        for (int k = 0; k < 8; k++) {
            float4 q = qa[k];
            __stcs(oqA + k, q);
            float xx, xy, xz, xw;
            upk2(xA0[k], xx, xy); upk2(xA1[k], xz, xw);
            float4 p;
            p.x = xx + (q.x - xx); p.y = xy + (q.y - xy);
            p.z = xz + (q.z - xz); p.w = xw + (q.w - xw);
            __stcs(opA + k, p);
        }
        #pragma unroll
        for (int k = 0; k < 8; k++) {
            float4 q = qb[k];
            __stcs(oqB + k, q);
            float xx, xy, xz, xw;
            upk2(xB0[k], xx, xy); upk2(xB1[k], xz, xw);
            float4 p;
            p.x = xx + (q.x - xx); p.y = xy + (q.y - xy);
            p.z = xz + (q.z - xz); p.w = xw + (q.w - xw);
            __stcs(opB + k, p);
        }
    }
}

// ---------------- generic fallback: 1 row/thread (R4-proven numerics) -------
__global__ void __launch_bounds__(128, 8) vq_fused1_kernel(
    const float* __restrict__ latent,
    const float* __restrict__ cb,
    float* __restrict__ out,
    int n_rows)
{
    __shared__ float s_cb[KCODES * DDIM];
    __shared__ float s_nrm[KCODES];

    const int tid  = threadIdx.x;
    const int gtid = blockIdx.x * 128 + tid;
    const bool active = gtid < n_rows;

    float4 xv[8];
    const float4* xr4 = reinterpret_cast<const float4*>(latent) + (size_t)gtid * 8;
    if (active) {
        #pragma unroll
        for (int k = 0; k < 8; k++) xv[k] = xr4[k];
    }

    float4* s_cb4 = reinterpret_cast<float4*>(s_cb);
    const float4* cb4 = reinterpret_cast<const float4*>(cb);
    #pragma unroll
    for (int i = 0; i < 8; i++) s_cb4[tid + i * 128] = cb4[tid + i * 128];
    __syncthreads();

    {
        float s = 0.f;
        #pragma unroll
        for (int d = 0; d < DDIM; d++) { float v = s_cb[tid * DDIM + d]; s += v * v; }
        s_nrm[tid] = s;
    }
    __syncthreads();

    const size_t n_lat = (size_t)n_rows * DDIM;
    float* out_quant = out + n_lat;
    float4* out_cs4  = reinterpret_cast<float4*>(out + 2 * n_lat);
    const size_t nth = (size_t)gridDim.x * 128;

    unsigned long long xp0[8], xp1[8];
    float A = 0.f;
    if (active) {
        float a0 = 0.f, a1 = 0.f, a2 = 0.f, a3 = 0.f;
        #pragma unroll
        for (int k = 0; k < 8; k++) {
            a0 = fmaf(xv[k].x, xv[k].x, a0);
            a1 = fmaf(xv[k].y, xv[k].y, a1);
            a2 = fmaf(xv[k].z, xv[k].z, a2);
            a3 = fmaf(xv[k].w, xv[k].w, a3);
            xp0[k] = pk2(xv[k].x, xv[k].y);
            xp1[k] = pk2(xv[k].z, xv[k].w);
        }
        A = (a0 + a1) + (a2 + a3);
    }

    const size_t total4 = (size_t)n_rows * 128;
    for (size_t i4 = (size_t)gtid; i4 < total4; i4 += nth)
        __stcs(&out_cs4[i4], s_cb4[i4 & 1023]);

    if (!active) return;

    float best = 3.0e38f;
    int   bi   = 0;
    const ulonglong2* scb2 = reinterpret_cast<const ulonglong2*>(s_cb);
    #pragma unroll 2
    for (int j = 0; j < KCODES; j++) {
        unsigned long long acc0 = 0ull, acc1 = 0ull;
        const ulonglong2* cj = scb2 + j * 8;
        #pragma unroll
        for (int k = 0; k < 8; k++) {
            ulonglong2 c = cj[k];
            fma2(acc0, xp0[k], c.x);
            fma2(acc1, xp1[k], c.y);
        }
        unsigned long long accs;
        asm("add.rn.f32x2 %0, %1, %2;" : "=l"(accs) : "l"(acc0), "l"(acc1));
        float lo, hi; upk2(accs, lo, hi);
        float d = fmaf(-2.0f, lo + hi, A + s_nrm[j]);
        if (d < best) { best = d; bi = j; }
    }

    const float4* q4 = reinterpret_cast<const float4*>(s_cb + bi * DDIM);
    float4* oq = reinterpret_cast<float4*>(out_quant) + (size_t)gtid * 8;
    float4* op = reinterpret_cast<float4*>(out)       + (size_t)gtid * 8;
    #pragma unroll
    for (int k = 0; k < 8; k++) {
        float4 q = q4[k];
        __stcs(oq + k, q);
        float xx, xy, xz, xw;
        upk2(xp0[k], xx, xy); upk2(xp1[k], xz, xw);
        float4 p;
        p.x = xx + (q.x - xx); p.y = xy + (q.y - xy);
        p.z = xz + (q.z - xz); p.w = xw + (q.w - xw);
        __stcs(op + k, p);
    }
}

extern "C" void kernel_launch(void* const* d_in, const int* in_sizes, int n_in,
                              void* d_out, int out_size)
{
    const float* latent = (const float*)d_in[0];
    const float* cb     = (const float*)d_in[1];
    int sz0 = in_sizes[0], sz1 = in_sizes[1];
    if (sz0 < sz1) {  // safety: latent is the big tensor
        const float* t = latent; latent = cb; cb = t;
        int ts = sz0; sz0 = sz1; sz1 = ts;
    }
    (void)n_in; (void)out_size;
    int n_rows = sz0 / DDIM;                         // 131072
    if ((n_rows % 128) == 0 && ((n_rows / 2) % 1024) == 0) {
        vq_fused2_kernel<<<n_rows / 128, 64>>>(latent, cb, (float*)d_out, n_rows);
    } else {
        vq_fused1_kernel<<<(n_rows + 127) / 128, 128>>>(latent, cb, (float*)d_out, n_rows);
    }
}

// round 7
// speedup vs baseline: 1.0283x; 1.0283x over previous
#include <cuda_runtime.h>
#include <cstdint>

// TranVectorQuantizer: latent [16384,8,32] f32, codebook [128,32] f32.
// Outputs concatenated in d_out (all f32):
//   [0,        4194304)  policy_vq_latent = latent + (quantized - latent)
//   [4194304,  8388608)  quantized_latent = codebook[argmin_j dist(x, c_j)]
//   [8388608, 75497472)  codebook_set = codebook tiled 16384x
//
// Distance reproduces the reference arithmetic EXACTLY (rel_err 0.0 verified):
//   d_j = fmaf(-2, M_j, fl(A + B_j)), fixed f32x2 FMA chain order for M_j.
// DO NOT change the FMA chain order or the snapping add: tie-breaking on the
// ~ulp(32) distance grid depends on it.
//
// R5 structure: 2 rows per thread so each codebook LDS (the dominant L1TEX
// consumer at 89% in R4) feeds two dot chains; codebook_set broadcast stores
// stay interleaved with the argmin loop (2 per code) to overlap DRAM drain.

#define DDIM 32
#define KCODES 128

static __device__ __forceinline__ unsigned long long pk2(float a, float b) {
    unsigned long long r;
    asm("mov.b64 %0, {%1, %2};" : "=l"(r) : "f"(a), "f"(b));
    return r;
}
static __device__ __forceinline__ void upk2(unsigned long long p, float& a, float& b) {
    asm("mov.b64 {%0, %1}, %2;" : "=f"(a), "=f"(b) : "l"(p));
}
static __device__ __forceinline__ void fma2(unsigned long long& acc,
                                            unsigned long long x,
                                            unsigned long long c) {
    asm("fma.rn.f32x2 %0, %1, %2, %0;" : "+l"(acc) : "l"(x), "l"(c));
}

// ---------------- exact kernel: n_rows % 128 == 0, 2 rows/thread ------------
__global__ void __launch_bounds__(64, 8) vq_fused2_kernel(
    const float* __restrict__ latent,
    const float* __restrict__ cb,
    float* __restrict__ out,
    int n_rows)
{
    __shared__ float s_cb[KCODES * DDIM];   // 16 KB
    __shared__ float s_nrm[KCODES];

    const int tid  = threadIdx.x;
    const int gt   = blockIdx.x * 64 + tid;          // global thread id
    const int rowA = blockIdx.x * 128 + tid;
    const int rowB = rowA + 64;

    // ---- issue both latent rows early (overlaps codebook staging) ----
    const float4* la = reinterpret_cast<const float4*>(latent) + (size_t)rowA * 8;
    const float4* lb = reinterpret_cast<const float4*>(latent) + (size_t)rowB * 8;
    float4 xa[8], xb[8];
    #pragma unroll
    for (int k = 0; k < 8; k++) { xa[k] = la[k]; xb[k] = lb[k]; }

    // ---- stage codebook ----
    float4* s_cb4 = reinterpret_cast<float4*>(s_cb);
    const float4* cb4 = reinterpret_cast<const float4*>(cb);
    #pragma unroll
    for (int i = 0; i < 16; i++) s_cb4[tid + i * 64] = cb4[tid + i * 64];
    __syncthreads();

    #pragma unroll
    for (int h = 0; h < 2; h++) {        // same per-code accumulation order as R4
        int c = tid + h * 64;
        float s = 0.f;
        #pragma unroll
        for (int d = 0; d < DDIM; d++) { float v = s_cb[c * DDIM + d]; s += v * v; }
        s_nrm[c] = s;
    }
    __syncthreads();

    // ---- pack rows + A (identical numerics per row to R4) ----
    unsigned long long xA0[8], xA1[8], xB0[8], xB1[8];
    float AA, AB;
    {
        float a0 = 0.f, a1 = 0.f, a2 = 0.f, a3 = 0.f;
        #pragma unroll
        for (int k = 0; k < 8; k++) {
            a0 = fmaf(xa[k].x, xa[k].x, a0);
            a1 = fmaf(xa[k].y, xa[k].y, a1);
            a2 = fmaf(xa[k].z, xa[k].z, a2);
            a3 = fmaf(xa[k].w, xa[k].w, a3);
            xA0[k] = pk2(xa[k].x, xa[k].y);
            xA1[k] = pk2(xa[k].z, xa[k].w);
        }
        AA = (a0 + a1) + (a2 + a3);
    }
    {
        float a0 = 0.f, a1 = 0.f, a2 = 0.f, a3 = 0.f;
        #pragma unroll
        for (int k = 0; k < 8; k++) {
            a0 = fmaf(xb[k].x, xb[k].x, a0);
            a1 = fmaf(xb[k].y, xb[k].y, a1);
            a2 = fmaf(xb[k].z, xb[k].z, a2);
            a3 = fmaf(xb[k].w, xb[k].w, a3);
            xB0[k] = pk2(xb[k].x, xb[k].y);
            xB1[k] = pk2(xb[k].z, xb[k].w);
        }
        AB = (a0 + a1) + (a2 + a3);
    }

    const size_t n_lat = (size_t)n_rows * DDIM;
    float* out_quant = out + n_lat;
    float4* out_cs4  = reinterpret_cast<float4*>(out + 2 * n_lat);
    const size_t nth = (size_t)gridDim.x * 64;       // == n_rows/2, multiple of 1024

    float bestA = 3.0e38f, bestB = 3.0e38f;
    int   biA = 0, biB = 0;
    const ulonglong2* scb2 = reinterpret_cast<const ulonglong2*>(s_cb);

    // stride preserves (index & 1023): one register-held broadcast value
    float4 vbc = s_cb4[gt & 1023];
    float4* csp = out_cs4 + gt;

    for (int j = 0; j < KCODES; j++) {
        __stcs(csp, vbc);                 // 2 interleaved codebook_set stores
        __stcs(csp + nth, vbc);
        csp += 2 * nth;

        unsigned long long aA0 = 0ull, aA1 = 0ull, aB0 = 0ull, aB1 = 0ull;
        const ulonglong2* cj = scb2 + j * 8;          // broadcast LDS, shared by both rows
        #pragma unroll
        for (int k = 0; k < 8; k++) {
            ulonglong2 c = cj[k];
            fma2(aA0, xA0[k], c.x);
            fma2(aA1, xA1[k], c.y);
            fma2(aB0, xB0[k], c.x);
            fma2(aB1, xB1[k], c.y);
        }
        float nrm = s_nrm[j];
        unsigned long long sA, sB;
        asm("add.rn.f32x2 %0, %1, %2;" : "=l"(sA) : "l"(aA0), "l"(aA1));
        asm("add.rn.f32x2 %0, %1, %2;" : "=l"(sB) : "l"(aB0), "l"(aB1));
        float lo, hi;
        upk2(sA, lo, hi);
        float dA = fmaf(-2.0f, lo + hi, AA + nrm);    // fl(S - 2M), single rounding
        upk2(sB, lo, hi);
        float dB = fmaf(-2.0f, lo + hi, AB + nrm);
        if (dA < bestA) { bestA = dA; biA = j; }      // strict <: first index on ties
        if (dB < bestB) { bestB = dB; biB = j; }
    }

    // ---- write quantized + policy for both rows (x from packs: bit-identical) ----
    {
        const float4* qa = reinterpret_cast<const float4*>(s_cb + biA * DDIM);
        const float4* qb = reinterpret_cast<const float4*>(s_cb + biB * DDIM);
        float4* oqA = reinterpret_cast<float4*>(out_quant) + (size_t)rowA * 8;
        float4* opA = reinterpret_cast<float4*>(out)       + (size_t)rowA * 8;
        float4* oqB = reinterpret_cast<float4*>(out_quant) + (size_t)rowB * 8;
        float4* opB = reinterpret_cast<float4*>(out)       + (size_t)rowB * 8;
        #pragma unroll
        for (int k = 0; k < 8; k++) {
            float4 q = qa[k];
            __stcs(oqA + k, q);
            float xx, xy, xz, xw;
            upk2(xA0[k], xx, xy); upk2(xA1[k], xz, xw);
            float4 p;
            p.x = xx + (q.x - xx); p.y = xy + (q.y - xy);
            p.z = xz + (q.z - xz); p.w = xw + (q.w - xw);
            __stcs(opA + k, p);
        }
        #pragma unroll
        for (int k = 0; k < 8; k++) {
            float4 q = qb[k];
            __stcs(oqB + k, q);
            float xx, xy, xz, xw;
            upk2(xB0[k], xx, xy); upk2(xB1[k], xz, xw);
            float4 p;
            p.x = xx + (q.x - xx); p.y = xy + (q.y - xy);
            p.z = xz + (q.z - xz); p.w = xw + (q.w - xw);
            __stcs(opB + k, p);
        }
    }
}

// ---------------- generic fallback: 1 row/thread (R4-proven numerics) -------
__global__ void __launch_bounds__(128, 8) vq_fused1_kernel(
    const float* __restrict__ latent,
    const float* __restrict__ cb,
    float* __restrict__ out,
    int n_rows)
{
    __shared__ float s_cb[KCODES * DDIM];
    __shared__ float s_nrm[KCODES];

    const int tid  = threadIdx.x;
    const int gtid = blockIdx.x * 128 + tid;
    const bool active = gtid < n_rows;

    float4 xv[8];
    const float4* xr4 = reinterpret_cast<const float4*>(latent) + (size_t)gtid * 8;
    if (active) {
        #pragma unroll
        for (int k = 0; k < 8; k++) xv[k] = xr4[k];
    }

    float4* s_cb4 = reinterpret_cast<float4*>(s_cb);
    const float4* cb4 = reinterpret_cast<const float4*>(cb);
    #pragma unroll
    for (int i = 0; i < 8; i++) s_cb4[tid + i * 128] = cb4[tid + i * 128];
    __syncthreads();

    {
        float s = 0.f;
        #pragma unroll
        for (int d = 0; d < DDIM; d++) { float v = s_cb[tid * DDIM + d]; s += v * v; }
        s_nrm[tid] = s;
    }
    __syncthreads();

    const size_t n_lat = (size_t)n_rows * DDIM;
    float* out_quant = out + n_lat;
    float4* out_cs4  = reinterpret_cast<float4*>(out + 2 * n_lat);
    const size_t nth = (size_t)gridDim.x * 128;

    unsigned long long xp0[8], xp1[8];
    float A = 0.f;
    if (active) {
        float a0 = 0.f, a1 = 0.f, a2 = 0.f, a3 = 0.f;
        #pragma unroll
        for (int k = 0; k < 8; k++) {
            a0 = fmaf(xv[k].x, xv[k].x, a0);
            a1 = fmaf(xv[k].y, xv[k].y, a1);
            a2 = fmaf(xv[k].z, xv[k].z, a2);
            a3 = fmaf(xv[k].w, xv[k].w, a3);
            xp0[k] = pk2(xv[k].x, xv[k].y);
            xp1[k] = pk2(xv[k].z, xv[k].w);
        }
        A = (a0 + a1) + (a2 + a3);
    }

    const size_t total4 = (size_t)n_rows * 128;
    for (size_t i4 = (size_t)gtid; i4 < total4; i4 += nth)
        __stcs(&out_cs4[i4], s_cb4[i4 & 1023]);

    if (!active) return;

    float best = 3.0e38f;
    int   bi   = 0;
    const ulonglong2* scb2 = reinterpret_cast<const ulonglong2*>(s_cb);
    #pragma unroll 2
    for (int j = 0; j < KCODES; j++) {
        unsigned long long acc0 = 0ull, acc1 = 0ull;
        const ulonglong2* cj = scb2 + j * 8;
        #pragma unroll
        for (int k = 0; k < 8; k++) {
            ulonglong2 c = cj[k];
            fma2(acc0, xp0[k], c.x);
            fma2(acc1, xp1[k], c.y);
        }
        unsigned long long accs;
        asm("add.rn.f32x2 %0, %1, %2;" : "=l"(accs) : "l"(acc0), "l"(acc1));
        float lo, hi; upk2(accs, lo, hi);
        float d = fmaf(-2.0f, lo + hi, A + s_nrm[j]);
        if (d < best) { best = d; bi = j; }
    }

    const float4* q4 = reinterpret_cast<const float4*>(s_cb + bi * DDIM);
    float4* oq = reinterpret_cast<float4*>(out_quant) + (size_t)gtid * 8;
    float4* op = reinterpret_cast<float4*>(out)       + (size_t)gtid * 8;
    #pragma unroll
    for (int k = 0; k < 8; k++) {
        float4 q = q4[k];
        __stcs(oq + k, q);
        float xx, xy, xz, xw;
        upk2(xp0[k], xx, xy); upk2(xp1[k], xz, xw);
        float4 p;
        p.x = xx + (q.x - xx); p.y = xy + (q.y - xy);
        p.z = xz + (q.z - xz); p.w = xw + (q.w - xw);
        __stcs(op + k, p);
    }
}

extern "C" void kernel_launch(void* const* d_in, const int* in_sizes, int n_in,
                              void* d_out, int out_size)
{
    const float* latent = (const float*)d_in[0];
    const float* cb     = (const float*)d_in[1];
    int sz0 = in_sizes[0], sz1 = in_sizes[1];
    if (sz0 < sz1) {  // safety: latent is the big tensor
        const float* t = latent; latent = cb; cb = t;
        int ts = sz0; sz0 = sz1; sz1 = ts;
    }
    (void)n_in; (void)out_size;
    int n_rows = sz0 / DDIM;                         // 131072
    if ((n_rows % 128) == 0 && ((n_rows / 2) % 1024) == 0) {
        vq_fused2_kernel<<<n_rows / 128, 64>>>(latent, cb, (float*)d_out, n_rows);
    } else {
        vq_fused1_kernel<<<(n_rows + 127) / 128, 128>>>(latent, cb, (float*)d_out, n_rows);
    }
}